// round 1
// baseline (speedup 1.0000x reference)
#include <cuda_runtime.h>
#include <math.h>

#define N 3072
#define F 128
#define E 24576
#define TWOE 49152
#define NNW (N * N / 32)   // bitmap words

// ---------------- static scratch (no allocations allowed) ----------------
__device__ float    g_a[N];
__device__ float    g_c[N];
__device__ unsigned g_bitmap[NNW];      // dedup of directed pairs (1.18 MB)
__device__ int      g_epq[TWOE];        // deduped directed edges, packed (p<<16)|q
__device__ float    g_ee[TWOE];         // their scores
__device__ int      g_cpq[TWOE];        // deduped contraction edges (e>0)
__device__ int      g_nedges;
__device__ int      g_ncedges;
__device__ int      g_deg[N];           // incident-to-contraction flag
__device__ int      g_cluster[N];
__device__ float    g_y[N * F];         // y = S^T x accumulator (node space)

// ---------------- kernels ----------------

__global__ void k_init() {
    int i = blockIdx.x * blockDim.x + threadIdx.x;
    int s = gridDim.x * blockDim.x;
    for (int j = i; j < NNW; j += s) g_bitmap[j] = 0u;
    for (int j = i; j < N * F; j += s) g_y[j] = 0.0f;
    for (int j = i; j < N; j += s) g_deg[j] = 0;
    if (i == 0) { g_nedges = 0; g_ncedges = 0; }
}

__global__ void k_zero_out(float* p, long long n) {
    long long i = (long long)blockIdx.x * blockDim.x + threadIdx.x;
    long long s = (long long)gridDim.x * blockDim.x;
    long long n4 = n >> 2;
    float4* p4 = (float4*)p;
    float4 z = make_float4(0.f, 0.f, 0.f, 0.f);
    for (long long j = i; j < n4; j += s) p4[j] = z;
    for (long long j = (n4 << 2) + i; j < n; j += s) p[j] = 0.0f;
}

// per-node dots a[i]=x[i]·w[0:128], c[i]=x[i]·w[128:256]; block=128, grid=N
__global__ void k_dots(const float* __restrict__ x, const float* __restrict__ w) {
    int i = blockIdx.x, t = threadIdx.x;
    float xv = x[i * F + t];
    float pa = xv * w[t];
    float pc = xv * w[F + t];
    #pragma unroll
    for (int o = 16; o; o >>= 1) {
        pa += __shfl_down_sync(0xffffffffu, pa, o);
        pc += __shfl_down_sync(0xffffffffu, pc, o);
    }
    __shared__ float sa[4], sc[4];
    if ((t & 31) == 0) { sa[t >> 5] = pa; sc[t >> 5] = pc; }
    __syncthreads();
    if (t == 0) {
        g_a[i] = sa[0] + sa[1] + sa[2] + sa[3];
        g_c[i] = sc[0] + sc[1] + sc[2] + sc[3];
    }
}

// per input edge: both directions; dedup-claim, score, flag degrees
__global__ void k_edges(const int* __restrict__ ei, const float* __restrict__ bptr) {
    int k = blockIdx.x * blockDim.x + threadIdx.x;
    if (k >= E) return;
    int u = ei[k], v = ei[E + k];
    if (u == v) return;                    // self-loops removed everywhere
    float b = *bptr;
    #pragma unroll
    for (int d = 0; d < 2; d++) {
        int p = d ? v : u;
        int q = d ? u : v;
        float z = g_a[p] + g_c[q] + b;
        float e = tanhf(z);
        if (e > 0.0f) { g_deg[p] = 1; g_deg[q] = 1; }
        unsigned idx = (unsigned)p * N + (unsigned)q;
        unsigned bit = 1u << (idx & 31u);
        unsigned old = atomicOr(&g_bitmap[idx >> 5], bit);
        if (!(old & bit)) {                // first claimer of this ordered pair
            int s = atomicAdd(&g_nedges, 1);
            g_epq[s] = (p << 16) | q;
            g_ee[s] = e;
            if (e > 0.0f) {
                int t2 = atomicAdd(&g_ncedges, 1);
                g_cpq[t2] = (p << 16) | q;
            }
        }
    }
}

// directed min-label reachability + cluster ranking. Single block, 1024 thr.
__global__ void k_cc() {
    __shared__ int lab[N];
    __shared__ int cum[N];
    __shared__ int scan[1024];
    __shared__ int changed;
    int t = threadIdx.x;
    for (int i = t; i < N; i += 1024) lab[i] = i;
    int M = g_ncedges;
    __syncthreads();

    for (;;) {
        if (t == 0) changed = 0;
        __syncthreads();
        // edge relaxation: labels[p] = min(labels[p], labels[q]) for p->q
        for (int k = t; k < M; k += 1024) {
            int pq = g_cpq[k];
            int p = pq >> 16, q = pq & 0xFFFF;
            int lq = lab[q];
            if (lq < lab[p]) { atomicMin(&lab[p], lq); changed = 1; }
        }
        __syncthreads();
        // pointer jumping
        for (int i = t; i < N; i += 1024) {
            int l = lab[i];
            int m = lab[l];
            if (m < l) { atomicMin(&lab[i], m); changed = 1; }
        }
        __syncthreads();
        if (!changed) break;
        __syncthreads();   // protect 'changed' reset at loop top
    }

    // roots + inclusive prefix sum over 3072 (1024 threads x 3 elems)
    for (int i = t; i < N; i += 1024) cum[i] = (lab[i] == i) ? 1 : 0;
    __syncthreads();
    int base = t * 3;
    int s0 = cum[base];
    int s1 = s0 + cum[base + 1];
    int s2 = s1 + cum[base + 2];
    scan[t] = s2;
    __syncthreads();
    for (int off = 1; off < 1024; off <<= 1) {
        int v = scan[t];
        int w2 = (t >= off) ? scan[t - off] : 0;
        __syncthreads();
        scan[t] = v + w2;
        __syncthreads();
    }
    int excl = (t == 0) ? 0 : scan[t - 1];
    cum[base]     = excl + s0;
    cum[base + 1] = excl + s1;
    cum[base + 2] = excl + s2;
    __syncthreads();
    for (int i = t; i < N; i += 1024) g_cluster[i] = cum[lab[i]] - 1;
}

// y[v] += e * x[u] for each deduped directed edge; block per edge, 128 thr
__global__ void k_y(const float* __restrict__ x) {
    int k = blockIdx.x;
    if (k >= g_nedges) return;
    int pq = g_epq[k];
    int u = pq >> 16, v = pq & 0xFFFF;
    float e = g_ee[k];
    int t = threadIdx.x;
    atomicAdd(&g_y[v * F + t], e * x[u * F + t]);
}

// X_new[cluster[v]] += y[v] (+ x[v] if isolated under contraction)
__global__ void k_x(const float* __restrict__ x, float* __restrict__ Xout) {
    int v = blockIdx.x, t = threadIdx.x;
    float val = g_y[v * F + t];
    if (g_deg[v] == 0) val += x[v * F + t];
    atomicAdd(&Xout[g_cluster[v] * F + t], val);
}

// A_new[p,q] += 1 per deduped directed edge across clusters
__global__ void k_a(float* __restrict__ Aout) {
    int k = blockIdx.x * blockDim.x + threadIdx.x;
    if (k >= g_nedges) return;
    int pq = g_epq[k];
    int u = pq >> 16, v = pq & 0xFFFF;
    int p = g_cluster[u], q = g_cluster[v];
    if (p != q) atomicAdd(&Aout[(long long)p * N + q], 1.0f);
}

// new_batch zeros (already zeroed) + cluster as float
__global__ void k_tail(float* __restrict__ out_batch, float* __restrict__ out_cluster) {
    int i = blockIdx.x * blockDim.x + threadIdx.x;
    if (i < N) {
        out_batch[i] = 0.0f;
        out_cluster[i] = (float)g_cluster[i];
    }
}

// ---------------- launcher ----------------
extern "C" void kernel_launch(void* const* d_in, const int* in_sizes, int n_in,
                              void* d_out, int out_size) {
    const float* x  = (const float*)d_in[0];
    const int*   ei = (const int*)d_in[1];
    // d_in[2] = batch (all zeros, unused)
    const float* w  = (const float*)d_in[3];
    const float* b  = (const float*)d_in[4];

    float* out = (float*)d_out;
    float* Xout      = out;                       // [N, F]
    float* Aout      = out + (long long)N * F;    // [N, N]
    float* Bout      = Aout + (long long)N * N;   // [N]
    float* Cout      = Bout + N;                  // [N]

    k_init<<<256, 256>>>();
    k_zero_out<<<2048, 256>>>(out, (long long)out_size);
    k_dots<<<N, F>>>(x, w);
    k_edges<<<(E + 127) / 128, 128>>>(ei, b);
    k_cc<<<1, 1024>>>();
    k_y<<<TWOE, F>>>(x);
    k_x<<<N, F>>>(x, Xout);
    k_a<<<(TWOE + 127) / 128, 128>>>(Aout);
    k_tail<<<(N + 255) / 256, 256>>>(Bout, Cout);
}

// round 2
// speedup vs baseline: 1.3017x; 1.3017x over previous
#include <cuda_runtime.h>
#include <math.h>

#define N 3072
#define F 128
#define E 24576
#define TWOE 49152
#define NNW (N * N / 32)   // dedup bitmap words

// ---------------- static scratch ----------------
__device__ float    g_a[N];
__device__ float    g_c[N];
__device__ unsigned g_bitmap[NNW];      // dedup of directed pairs (1.18 MB)
__device__ int      g_epq[TWOE];        // deduped directed edges, packed (p<<16)|q
__device__ float    g_ee[TWOE];         // their scores
__device__ int      g_cpq[TWOE];        // deduped contraction edges (e>0)
__device__ int      g_nedges;
__device__ int      g_ncedges;
__device__ int      g_indeg[N];         // deduped in-degree per destination
__device__ int      g_offs[N];          // exclusive scan of indeg
__device__ int      g_cnt[N];           // scatter cursors
__device__ int      g_srci[TWOE];       // CSR: source node per slot
__device__ float    g_wv[TWOE];         // CSR: weight per slot
__device__ int      g_deg[N];           // incident-to-contraction flag
__device__ int      g_cluster[N];

// ---------------- kernels ----------------

// zero everything: scratch + whole output buffer (poisoned by harness)
__global__ void k_zero(float* out, long long n) {
    long long i = (long long)blockIdx.x * blockDim.x + threadIdx.x;
    long long s = (long long)gridDim.x * blockDim.x;
    long long n4 = n >> 2;
    float4* p4 = (float4*)out;
    float4 z = make_float4(0.f, 0.f, 0.f, 0.f);
    for (long long j = i; j < n4; j += s) p4[j] = z;
    for (long long j = (n4 << 2) + i; j < n; j += s) out[j] = 0.0f;
    uint4* b4 = (uint4*)g_bitmap;
    uint4 uz = make_uint4(0u, 0u, 0u, 0u);
    for (long long j = i; j < NNW / 4; j += s) b4[j] = uz;
    for (long long j = i; j < N; j += s) { g_indeg[j] = 0; g_cnt[j] = 0; g_deg[j] = 0; }
    if (i == 0) { g_nedges = 0; g_ncedges = 0; }
}

// per-node dots a[i]=x[i]·w[0:128], c[i]=x[i]·w[128:256]
__global__ void k_dots(const float* __restrict__ x, const float* __restrict__ w) {
    int i = blockIdx.x, t = threadIdx.x;
    float xv = x[i * F + t];
    float pa = xv * w[t];
    float pc = xv * w[F + t];
    #pragma unroll
    for (int o = 16; o; o >>= 1) {
        pa += __shfl_down_sync(0xffffffffu, pa, o);
        pc += __shfl_down_sync(0xffffffffu, pc, o);
    }
    __shared__ float sa[4], sc[4];
    if ((t & 31) == 0) { sa[t >> 5] = pa; sc[t >> 5] = pc; }
    __syncthreads();
    if (t == 0) {
        g_a[i] = sa[0] + sa[1] + sa[2] + sa[3];
        g_c[i] = sc[0] + sc[1] + sc[2] + sc[3];
    }
}

// per input edge: both directions; dedup, warp-aggregated compaction
__global__ void k_edges(const int* __restrict__ ei, const float* __restrict__ bptr) {
    int k = blockIdx.x * blockDim.x + threadIdx.x;   // grid covers exactly E
    int u = ei[k], v = ei[E + k];
    bool valid = (u != v);
    float b = *bptr;
    int lane = threadIdx.x & 31;
    unsigned lt = (1u << lane) - 1u;
    #pragma unroll
    for (int d = 0; d < 2; d++) {
        int p = d ? v : u;
        int q = d ? u : v;
        float e = 0.0f;
        bool win = false;
        if (valid) {
            e = tanhf(g_a[p] + g_c[q] + b);
            if (e > 0.0f) { g_deg[p] = 1; g_deg[q] = 1; }
            unsigned idx = (unsigned)p * N + (unsigned)q;
            unsigned bit = 1u << (idx & 31u);
            unsigned old = atomicOr(&g_bitmap[idx >> 5], bit);
            win = !(old & bit);
        }
        // aggregate main-list append
        unsigned wm = __ballot_sync(0xffffffffu, win);
        if (wm) {
            int leader = __ffs(wm) - 1;
            int base;
            if (lane == leader) base = atomicAdd(&g_nedges, __popc(wm));
            base = __shfl_sync(0xffffffffu, base, leader);
            if (win) {
                int s = base + __popc(wm & lt);
                g_epq[s] = (p << 16) | q;
                g_ee[s] = e;
                atomicAdd(&g_indeg[q], 1);
            }
        }
        // aggregate contraction-list append
        bool cwin = win && (e > 0.0f);
        unsigned cm = __ballot_sync(0xffffffffu, cwin);
        if (cm) {
            int leader = __ffs(cm) - 1;
            int base;
            if (lane == leader) base = atomicAdd(&g_ncedges, __popc(cm));
            base = __shfl_sync(0xffffffffu, base, leader);
            if (cwin) g_cpq[base + __popc(cm & lt)] = (p << 16) | q;
        }
    }
}

// one block, 1024 threads: indeg exclusive scan, directed min-label CC, cluster ranking
__global__ void k_cc() {
    __shared__ int lab[N];
    __shared__ int tmp[N];
    __shared__ int scn[1024];
    __shared__ int changed;
    int t = threadIdx.x;
    int base = t * 3;

    // ---- exclusive scan of g_indeg -> g_offs ----
    for (int i = t; i < N; i += 1024) tmp[i] = g_indeg[i];
    __syncthreads();
    {
        int s0 = tmp[base];
        int s1 = s0 + tmp[base + 1];
        int s2 = s1 + tmp[base + 2];
        scn[t] = s2;
        __syncthreads();
        for (int off = 1; off < 1024; off <<= 1) {
            int v = scn[t];
            int w2 = (t >= off) ? scn[t - off] : 0;
            __syncthreads();
            scn[t] = v + w2;
            __syncthreads();
        }
        int excl = (t == 0) ? 0 : scn[t - 1];
        g_offs[base]     = excl;
        g_offs[base + 1] = excl + s0;
        g_offs[base + 2] = excl + s1;
    }

    // ---- CC: chaotic min-label relaxation + pointer jumping ----
    for (int i = t; i < N; i += 1024) lab[i] = i;
    int M = g_ncedges;
    __syncthreads();
    for (;;) {
        if (t == 0) changed = 0;
        __syncthreads();
        for (int k = t; k < M; k += 1024) {
            int pq = g_cpq[k];
            int p = pq >> 16, q = pq & 0xFFFF;
            int lq = lab[q];
            if (lq < lab[p]) { atomicMin(&lab[p], lq); changed = 1; }
        }
        __syncthreads();
        #pragma unroll
        for (int r = 0; r < 3; r++) {           // aggressive path compression
            for (int i = t; i < N; i += 1024) {
                int l = lab[i];
                int m = lab[l];
                if (m < l) { atomicMin(&lab[i], m); changed = 1; }
            }
            __syncthreads();
        }
        if (!changed) break;
        __syncthreads();
    }

    // ---- rank roots -> consecutive cluster ids ----
    for (int i = t; i < N; i += 1024) tmp[i] = (lab[i] == i) ? 1 : 0;
    __syncthreads();
    {
        int s0 = tmp[base];
        int s1 = s0 + tmp[base + 1];
        int s2 = s1 + tmp[base + 2];
        scn[t] = s2;
        __syncthreads();
        for (int off = 1; off < 1024; off <<= 1) {
            int v = scn[t];
            int w2 = (t >= off) ? scn[t - off] : 0;
            __syncthreads();
            scn[t] = v + w2;
            __syncthreads();
        }
        int excl = (t == 0) ? 0 : scn[t - 1];
        tmp[base]     = excl + s0;
        tmp[base + 1] = excl + s1;
        tmp[base + 2] = excl + s2;
    }
    __syncthreads();
    for (int i = t; i < N; i += 1024) g_cluster[i] = tmp[lab[i]] - 1;
}

// scatter edges into CSR slots + A_new counts + cluster output
__global__ void k_scatter(float* __restrict__ Aout, float* __restrict__ Cout) {
    int k = blockIdx.x * blockDim.x + threadIdx.x;
    if (k < N) Cout[k] = (float)g_cluster[k];
    if (k >= g_nedges) return;
    int pq = g_epq[k];
    int u = pq >> 16, v = pq & 0xFFFF;
    int pos = g_offs[v] + atomicAdd(&g_cnt[v], 1);
    g_srci[pos] = u;
    g_wv[pos] = g_ee[k];
    int p = g_cluster[u], q = g_cluster[v];
    if (p != q) atomicAdd(&Aout[(long long)p * N + q], 1.0f);
}

// per-destination gather (no atomics in node space) + scatter into X_new
__global__ void k_gather(const float* __restrict__ x, float* __restrict__ Xout) {
    int v = blockIdx.x, t = threadIdx.x;
    int beg = g_offs[v];
    int end = beg + g_indeg[v];
    float acc = 0.0f;
    for (int i = beg; i < end; i++) {
        int u = g_srci[i];
        acc += g_wv[i] * __ldg(&x[u * F + t]);
    }
    if (g_deg[v] == 0) acc += x[v * F + t];
    atomicAdd(&Xout[g_cluster[v] * F + t], acc);
}

// ---------------- launcher ----------------
extern "C" void kernel_launch(void* const* d_in, const int* in_sizes, int n_in,
                              void* d_out, int out_size) {
    const float* x  = (const float*)d_in[0];
    const int*   ei = (const int*)d_in[1];
    // d_in[2] = batch (all zeros, unused)
    const float* w  = (const float*)d_in[3];
    const float* b  = (const float*)d_in[4];

    float* out  = (float*)d_out;
    float* Xout = out;                        // [N, F]
    float* Aout = out + (long long)N * F;     // [N, N]
    float* Bout = Aout + (long long)N * N;    // [N] (zeros; k_zero handles)
    float* Cout = Bout + N;                   // [N]
    (void)Bout;

    k_zero<<<2048, 256>>>(out, (long long)out_size);
    k_dots<<<N, F>>>(x, w);
    k_edges<<<E / 128, 128>>>(ei, b);
    k_cc<<<1, 1024>>>();
    k_scatter<<<TWOE / 128, 128>>>(Aout, Cout);
    k_gather<<<N, F>>>(x, Xout);
}

// round 3
// speedup vs baseline: 1.5228x; 1.1699x over previous
#include <cuda_runtime.h>
#include <math.h>

#define N 3072
#define F 128
#define E 24576
#define TWOE 49152
#define NNW (N * N / 32)   // dedup bitmap words
#define STRIDE 96          // CSR slots per destination node (Poisson(16) indeg; huge margin)

// ---------------- static scratch ----------------
__device__ float    g_a[N];
__device__ float    g_c[N];
__device__ unsigned g_bitmap[NNW];        // dedup of directed pairs (1.18 MB)
__device__ int      g_cpq[TWOE];          // deduped contraction edges (e>0), packed (p<<16)|q
__device__ int      g_ncedges;
__device__ int      g_cnt[N];             // per-destination CSR cursor == indeg
__device__ int      g_srci[N * STRIDE];   // CSR: source node per slot
__device__ float    g_wv[N * STRIDE];     // CSR: weight per slot
__device__ int      g_deg[N];             // incident-to-contraction flag
__device__ int      g_cluster[N];

// ---------------- kernels ----------------

// big output zero (39 MB, poisoned by harness) — runs on side stream
__global__ void k_zero_out(float* out, long long n) {
    long long i = (long long)blockIdx.x * blockDim.x + threadIdx.x;
    long long s = (long long)gridDim.x * blockDim.x;
    long long n4 = n >> 2;
    float4* p4 = (float4*)out;
    float4 z = make_float4(0.f, 0.f, 0.f, 0.f);
    for (long long j = i; j < n4; j += s) p4[j] = z;
    for (long long j = (n4 << 2) + i; j < n; j += s) out[j] = 0.0f;
}

// per-node dots + scratch zeroing (bitmap, cursors, flags, counters)
__global__ void k_dots(const float* __restrict__ x, const float* __restrict__ w) {
    int i = blockIdx.x, t = threadIdx.x;
    // zero scratch: block i owns bitmap words [i*96, (i+1)*96) as 24 uint4
    if (t < 24) ((uint4*)g_bitmap)[i * 24 + t] = make_uint4(0u, 0u, 0u, 0u);
    if (t == 32) g_cnt[i] = 0;
    if (t == 33) g_deg[i] = 0;
    if (i == 0 && t == 34) g_ncedges = 0;

    float xv = x[i * F + t];
    float pa = xv * w[t];
    float pc = xv * w[F + t];
    #pragma unroll
    for (int o = 16; o; o >>= 1) {
        pa += __shfl_down_sync(0xffffffffu, pa, o);
        pc += __shfl_down_sync(0xffffffffu, pc, o);
    }
    __shared__ float sa[4], sc[4];
    if ((t & 31) == 0) { sa[t >> 5] = pa; sc[t >> 5] = pc; }
    __syncthreads();
    if (t == 0) {
        g_a[i] = sa[0] + sa[1] + sa[2] + sa[3];
        g_c[i] = sc[0] + sc[1] + sc[2] + sc[3];
    }
}

// per input edge, both directions: dedup-claim, score, write CSR slot directly
__global__ void k_edges(const int* __restrict__ ei, const float* __restrict__ bptr) {
    int k = blockIdx.x * blockDim.x + threadIdx.x;   // grid covers exactly E
    int u = ei[k], v = ei[E + k];
    bool valid = (u != v);
    float b = *bptr;
    int lane = threadIdx.x & 31;
    unsigned lt = (1u << lane) - 1u;
    #pragma unroll
    for (int d = 0; d < 2; d++) {
        int p = d ? v : u;
        int q = d ? u : v;
        float e = 0.0f;
        bool win = false;
        if (valid) {
            e = tanhf(g_a[p] + g_c[q] + b);
            if (e > 0.0f) { g_deg[p] = 1; g_deg[q] = 1; }
            unsigned idx = (unsigned)p * N + (unsigned)q;
            unsigned bit = 1u << (idx & 31u);
            unsigned old = atomicOr(&g_bitmap[idx >> 5], bit);
            win = !(old & bit);
        }
        if (win) {   // first claimer: take a CSR slot at destination q
            int pos = atomicAdd(&g_cnt[q], 1);
            g_srci[q * STRIDE + pos] = p;
            g_wv[q * STRIDE + pos] = e;
        }
        // warp-aggregated append to contraction edge list
        bool cwin = win && (e > 0.0f);
        unsigned cm = __ballot_sync(0xffffffffu, cwin);
        if (cm) {
            int leader = __ffs(cm) - 1;
            int base;
            if (lane == leader) base = atomicAdd(&g_ncedges, __popc(cm));
            base = __shfl_sync(0xffffffffu, base, leader);
            if (cwin) g_cpq[base + __popc(cm & lt)] = (p << 16) | q;
        }
    }
}

// one block, 1024 threads: directed min-label CC + cluster ranking (warp scans)
__global__ void __launch_bounds__(1024) k_cc() {
    __shared__ int lab[N];
    __shared__ int cum[N];
    __shared__ int wsum[32];
    __shared__ int changed;
    int t = threadIdx.x;
    int lane = t & 31, wid = t >> 5;

    for (int i = t; i < N; i += 1024) lab[i] = i;
    int M = g_ncedges;
    __syncthreads();

    for (;;) {
        if (t == 0) changed = 0;
        __syncthreads();
        // edge relaxation, unrolled x8 with batched loads (MLP)
        for (int base = t; base < M; base += 8 * 1024) {
            int pq[8];
            #pragma unroll
            for (int j = 0; j < 8; j++) {
                int k = base + j * 1024;
                pq[j] = (k < M) ? g_cpq[k] : -1;
            }
            #pragma unroll
            for (int j = 0; j < 8; j++) {
                if (pq[j] >= 0) {
                    int p = pq[j] >> 16, q = pq[j] & 0xFFFF;
                    int lq = lab[q];
                    if (lq < lab[p]) { atomicMin(&lab[p], lq); changed = 1; }
                }
            }
        }
        __syncthreads();
        // pointer jumping x2
        #pragma unroll
        for (int r = 0; r < 2; r++) {
            for (int i = t; i < N; i += 1024) {
                int l = lab[i];
                int m = lab[l];
                if (m < l) { atomicMin(&lab[i], m); changed = 1; }
            }
            __syncthreads();
        }
        if (!changed) break;
        __syncthreads();
    }

    // ---- rank roots -> consecutive ids, via warp shfl scans ----
    int base3 = t * 3;
    int f0 = (lab[base3]     == base3)     ? 1 : 0;
    int f1 = (lab[base3 + 1] == base3 + 1) ? 1 : 0;
    int f2 = (lab[base3 + 2] == base3 + 2) ? 1 : 0;
    int s = f0 + f1 + f2;
    int inc = s;
    #pragma unroll
    for (int off = 1; off < 32; off <<= 1) {
        int nv = __shfl_up_sync(0xffffffffu, inc, off);
        if (lane >= off) inc += nv;
    }
    if (lane == 31) wsum[wid] = inc;
    __syncthreads();
    if (wid == 0) {
        int v = wsum[lane];
        int vi = v;
        #pragma unroll
        for (int off = 1; off < 32; off <<= 1) {
            int nv = __shfl_up_sync(0xffffffffu, vi, off);
            if (lane >= off) vi += nv;
        }
        wsum[lane] = vi;
    }
    __syncthreads();
    int wexcl = (wid == 0) ? 0 : wsum[wid - 1];
    int excl = wexcl + inc - s;
    cum[base3]     = excl + f0;
    cum[base3 + 1] = excl + f0 + f1;
    cum[base3 + 2] = excl + f0 + f1 + f2;
    __syncthreads();
    for (int i = t; i < N; i += 1024) g_cluster[i] = cum[lab[i]] - 1;
}

// per-destination gather -> X_new, per-edge A counts, cluster output
__global__ void k_finish(const float* __restrict__ x, float* __restrict__ Xout,
                         float* __restrict__ Aout, float* __restrict__ Cout) {
    int v = blockIdx.x, t = threadIdx.x;
    __shared__ int su[STRIDE];
    __shared__ float sw[STRIDE];
    int deg = g_cnt[v];
    if (t < deg) { su[t] = g_srci[v * STRIDE + t]; sw[t] = g_wv[v * STRIDE + t]; }
    __syncthreads();

    float acc = 0.0f;
    for (int i = 0; i < deg; i++)
        acc += sw[i] * __ldg(&x[su[i] * F + t]);
    if (g_deg[v] == 0) acc += x[v * F + t];

    int cv = g_cluster[v];
    atomicAdd(&Xout[cv * F + t], acc);

    if (t < deg) {
        int p = g_cluster[su[t]];
        if (p != cv) atomicAdd(&Aout[(long long)p * N + cv], 1.0f);
    }
    if (t == 0) Cout[v] = (float)cv;
}

// ---------------- launcher ----------------
extern "C" void kernel_launch(void* const* d_in, const int* in_sizes, int n_in,
                              void* d_out, int out_size) {
    const float* x  = (const float*)d_in[0];
    const int*   ei = (const int*)d_in[1];
    // d_in[2] = batch (all zeros, unused)
    const float* w  = (const float*)d_in[3];
    const float* b  = (const float*)d_in[4];

    float* out  = (float*)d_out;
    float* Xout = out;                        // [N, F]
    float* Aout = out + (long long)N * F;     // [N, N]
    float* Bout = Aout + (long long)N * N;    // [N] zeros (k_zero_out)
    float* Cout = Bout + N;                   // [N]
    (void)Bout;

    // one-time side-stream/event creation (first call is uncaptured)
    static cudaStream_t s2 = (cudaStream_t)0;
    static cudaEvent_t evA = nullptr, evB = nullptr;
    static bool inited = false;
    if (!inited) {
        inited = true;
        if (cudaStreamCreateWithFlags(&s2, cudaStreamNonBlocking) != cudaSuccess)
            s2 = (cudaStream_t)0;
        cudaEventCreateWithFlags(&evA, cudaEventDisableTiming);
        cudaEventCreateWithFlags(&evB, cudaEventDisableTiming);
    }

    // fork: big output zero overlaps dots->edges->cc
    cudaEventRecord(evA, 0);
    cudaStreamWaitEvent(s2, evA, 0);
    k_zero_out<<<1024, 256, 0, s2>>>(out, (long long)out_size);
    cudaEventRecord(evB, s2);

    k_dots<<<N, F>>>(x, w);
    k_edges<<<E / 128, 128>>>(ei, b);
    k_cc<<<1, 1024>>>();

    // join before writing outputs
    cudaStreamWaitEvent(0, evB, 0);
    k_finish<<<N, F>>>(x, Xout, Aout, Cout);
}